// round 15
// baseline (speedup 1.0000x reference)
#include <cuda_runtime.h>
#include <cstdint>
#include <cstddef>

// Problem constants (fixed by the reference's setup_inputs)
#define B_   2
#define S_   2048
#define H_   256
#define NS_  512
#define NR_  512
#define DIN  768    // 3*H
#define DFF  3072   // 4*DIN
#define NBLK (S_ / 16)    // 128 fine (16-token) blocks per batch row
#define NCBLK (S_ / 256)  // 8 coarse (256-token) blocks per batch row
#define KSPLIT 12
#define MN   ((size_t)B_ * NR_ * H_)     // 524288 output elems

// Scratch (static device globals: allocation-free per harness rules)
__device__ float g_rel[(size_t)B_ * NR_ * DIN];        // 6 MB   rel_reps (tf32-rounded)
__device__ float g_h[(size_t)B_ * NR_ * DFF];          // 24 MB  hidden (tf32-rounded)
__device__ float g_pref[(size_t)B_ * S_ * H_];         // 4 MB   in-fine-block prefix max
__device__ float g_suff[(size_t)B_ * S_ * H_];         // 4 MB   in-fine-block suffix max
__device__ float g_fblk[(size_t)B_ * NBLK * H_];       // 256 KB fine block maxima
__device__ float g_prefF[(size_t)B_ * NBLK * H_];      // 256 KB in-coarse prefix of fine
__device__ float g_suffF[(size_t)B_ * NBLK * H_];      // 256 KB in-coarse suffix of fine
__device__ float g_cblk[(size_t)B_ * NCBLK * H_];      // 16 KB  coarse block maxima
__device__ float g_part[(size_t)KSPLIT * MN];          // 24 MB  split-K partials
__device__ float g_w1r[(size_t)DIN * DFF];             // 9.4 MB W1 tf32-rounded
__device__ float g_w2r[(size_t)DFF * H_];              // 3 MB   W2 tf32-rounded

__device__ __forceinline__ uint32_t f2tf32(float f) {
    uint32_t r;
    asm("cvt.rna.tf32.f32 %0, %1;" : "=r"(r) : "f"(f));
    return r;
}
__device__ __forceinline__ float tf32r(float f) { return __uint_as_float(f2tf32(f)); }

// ---------------------------------------------------------------------------
// Weight pre-round (both W1 and W2 in one launch): tf32_round, float4 vec.
// ---------------------------------------------------------------------------
__global__ void k_round(const float* __restrict__ in1, float* __restrict__ out1,
                        size_t n1,
                        const float* __restrict__ in2, float* __restrict__ out2) {
    size_t i = ((size_t)blockIdx.x * blockDim.x + threadIdx.x) * 4;
    const float* in = in1;
    float* out = out1;
    if (i >= n1) { i -= n1; in = in2; out = out2; }
    float4 v = *(const float4*)(in + i);
    v.x = tf32r(v.x); v.y = tf32r(v.y); v.z = tf32r(v.z); v.w = tf32r(v.w);
    *(float4*)(out + i) = v;
}

// ---------------------------------------------------------------------------
// Kernel 0: per-fine-block (16-token) prefix/suffix running maxima + block max.
// grid = B_*NBLK, 256 threads (one channel each).
//   pref[t] = max(tok[blk_start..t]),  suff[t] = max(tok[t..blk_end])
// ---------------------------------------------------------------------------
__global__ void k_scan(const float* __restrict__ tok) {
    const int blk = blockIdx.x;          // b*NBLK + j
    const int h = threadIdx.x;
    const size_t base = (size_t)blk * 16 * H_ + h;
    const float* p = tok + base;
    float* pp = g_pref + base;
    float* sp = g_suff + base;
    float v[16];
    #pragma unroll
    for (int i = 0; i < 16; i++) v[i] = p[(size_t)i * H_];
    float r = v[0];
    pp[0] = r;
    #pragma unroll
    for (int i = 1; i < 16; i++) { r = fmaxf(r, v[i]); pp[(size_t)i * H_] = r; }
    g_fblk[(size_t)blk * H_ + h] = r;
    r = v[15];
    sp[(size_t)15 * H_] = r;
    #pragma unroll
    for (int i = 14; i >= 0; i--) { r = fmaxf(r, v[i]); sp[(size_t)i * H_] = r; }
}

// ---------------------------------------------------------------------------
// Kernel 0b: per-coarse-block prefix/suffix over the 16 fine maxima + coarse max.
// grid = B_*NCBLK (16), 256 threads.
// ---------------------------------------------------------------------------
__global__ void k_scanF(void) {
    const int cb = blockIdx.x;           // b*NCBLK + c
    const int h = threadIdx.x;
    const size_t base = (size_t)cb * 16 * H_ + h;
    const float* p = g_fblk + base;
    float* pp = g_prefF + base;
    float* sp = g_suffF + base;
    float v[16];
    #pragma unroll
    for (int i = 0; i < 16; i++) v[i] = p[(size_t)i * H_];
    float r = v[0];
    pp[0] = r;
    #pragma unroll
    for (int i = 1; i < 16; i++) { r = fmaxf(r, v[i]); pp[(size_t)i * H_] = r; }
    g_cblk[(size_t)cb * H_ + h] = r;
    r = v[15];
    sp[(size_t)15 * H_] = r;
    #pragma unroll
    for (int i = 14; i >= 0; i--) { r = fmaxf(r, v[i]); sp[(size_t)i * H_] = r; }
}

// ---------------------------------------------------------------------------
// Kernel 1: rel_reps = [head | tail | context-maxpool], tf32-rounded at store.
// Segment [a,bnd) decomposes into O(1) loads via the scan tables:
//   same fine block           -> walk tokens (<=16)
//   else suff[a] + pref[bnd-1] covers the partial edge blocks exactly;
//   interior fine blocks: same coarse -> walk (<=15); else suffF + prefF +
//   interior coarse maxima (<=6). Exact-set decomposition (no superset).
// ---------------------------------------------------------------------------
__global__ void __launch_bounds__(256)
k_rel(const float* __restrict__ tok,
      const float* __restrict__ spans,
      const int* __restrict__ span_ids,
      const int* __restrict__ rel_ids,
      const float* __restrict__ negp) {
    const int br = blockIdx.x;           // b*NR + r
    const int b = br >> 9;
    const int h = threadIdx.x;
    const float neg = *negp;

    const int head = rel_ids[br * 2 + 0];
    const int tail = rel_ids[br * 2 + 1];
    const int sb = b * NS_;
    const int hs = span_ids[(sb + head) * 2 + 0];
    const int he = span_ids[(sb + head) * 2 + 1];
    const int ts = span_ids[(sb + tail) * 2 + 0];
    const int te = span_ids[(sb + tail) * 2 + 1];

    float* row = g_rel + (size_t)br * DIN;
    row[h]       = tf32r(spans[(size_t)(sb + head) * H_ + h]);
    row[H_ + h]  = tf32r(spans[(size_t)(sb + tail) * H_ + h]);

    const int lo = min(he, te);
    const int hi = max(hs, ts);

    int s1 = min(max(hs, lo), hi), e1 = min(max(he, lo), hi);
    int s2 = min(max(ts, lo), hi), e2 = min(max(te, lo), hi);
    if (s2 < s1) { int t = s1; s1 = s2; s2 = t; t = e1; e1 = e2; e2 = t; }
    if (s2 < e1) { e1 = max(e1, e2); s2 = e1; e2 = e1; }

    const size_t tokoff = (size_t)b * S_ * H_ + h;
    const float* tb  = tok + tokoff;
    const float* prp = g_pref + tokoff;
    const float* sfp = g_suff + tokoff;
    const size_t fbo = (size_t)b * NBLK * H_ + h;
    const float* fbp = g_fblk + fbo;
    const float* pFp = g_prefF + fbo;
    const float* sFp = g_suffF + fbo;
    const float* cbp = g_cblk + (size_t)b * NCBLK * H_ + h;
    float m = neg;

    const int seg_a[3] = { lo, e1, e2 };
    const int seg_b[3] = { s1, s2, hi };
    for (int s = 0; s < 3; s++) {
        const int a = seg_a[s], bnd = seg_b[s];
        if (a >= bnd) continue;
        const int last = bnd - 1;
        const int fa = a >> 4, fl = last >> 4;
        if (fa == fl) {
            for (int t = a; t <= last; t++) m = fmaxf(m, tb[(size_t)t * H_]);
            continue;
        }
        m = fmaxf(m, sfp[(size_t)a * H_]);       // [a, end of fa]
        m = fmaxf(m, prp[(size_t)last * H_]);    // [start of fl, last]
        const int ja = fa + 1, jb = fl;          // interior fine [ja, jb)
        if (ja >= jb) continue;
        const int lastf = jb - 1;
        const int ca = ja >> 4, cl = lastf >> 4;
        if (ca == cl) {
            for (int j = ja; j <= lastf; j++) m = fmaxf(m, fbp[(size_t)j * H_]);
            continue;
        }
        m = fmaxf(m, sFp[(size_t)ja * H_]);      // [ja, end of ca]
        m = fmaxf(m, pFp[(size_t)lastf * H_]);   // [start of cl, lastf]
        for (int c = ca + 1; c < cl; c++)        // interior coarse
            m = fmaxf(m, cbp[(size_t)c * H_]);
    }

    const int allneg = __syncthreads_and(m == neg);
    row[2 * H_ + h] = allneg ? 0.0f : tf32r(m);
}

// ---------------------------------------------------------------------------
// tf32 tensor-core GEMM (mma.sync m16n8k8), cp.async double-buffered,
// dynamic shared memory. All operands PRE-ROUNDED to tf32 -> fragment loads
// are raw LDS. SPLITK: blockIdx.z picks a K-chunk; partial -> C + z*M*N.
// ROUND_OUT: round stored outputs to tf32 (feeding the next GEMM).
// ---------------------------------------------------------------------------
__device__ __forceinline__ void cp_async16(uint32_t dst, const void* src) {
    asm volatile("cp.async.cg.shared.global [%0], [%1], 16;\n"
                 :: "r"(dst), "l"(src));
}

__device__ __forceinline__ void mma_tf32(float* c, const uint32_t* a, const uint32_t* b) {
    asm volatile(
        "mma.sync.aligned.m16n8k8.row.col.f32.tf32.tf32.f32 "
        "{%0,%1,%2,%3}, {%4,%5,%6,%7}, {%8,%9}, {%0,%1,%2,%3};"
        : "+f"(c[0]), "+f"(c[1]), "+f"(c[2]), "+f"(c[3])
        : "r"(a[0]), "r"(a[1]), "r"(a[2]), "r"(a[3]), "r"(b[0]), "r"(b[1]));
}

template <int BM, int BN, int BK, int WM, int WN, bool RELU, bool SPLITK, bool ROUND_OUT>
__global__ void __launch_bounds__((BM / WM) * (BN / WN) * 32)
k_tgemm(const float* __restrict__ A, const float* __restrict__ Bw,
        const float* __restrict__ bias, float* __restrict__ C,
        int M, int N, int K, int Ksplit) {
    constexpr int WARPS_M = BM / WM;
    constexpr int WARPS_N = BN / WN;
    constexpr int NT = WARPS_M * WARPS_N * 32;
    constexpr int ASTR = BK + 4;          // float stride; (BK+4)*4 % 16 == 0
    constexpr int BSTR = BN + 8;          // conflict-free fragment reads
    constexpr int MT = WM / 16;
    constexpr int NTL = WN / 8;
    constexpr int LDA = (BM * BK / 4) / NT;   // float4 loads per thread (A)
    constexpr int LDB = (BK * BN / 4) / NT;   // float4 loads per thread (B)
    constexpr int ASZ = BM * ASTR;
    constexpr int BSZ = BK * BSTR;

    extern __shared__ float dsm[];
    float* As = dsm;                 // [2][ASZ]
    float* Bs = dsm + 2 * ASZ;       // [2][BSZ]

    const int tid = threadIdx.x;
    const int bm = blockIdx.y * BM;
    const int bn = blockIdx.x * BN;
    const int k0 = SPLITK ? blockIdx.z * Ksplit : 0;
    if (SPLITK) C += (size_t)blockIdx.z * M * N;
    const int wid = tid >> 5, lane = tid & 31;
    const int gid = lane >> 2, tig = lane & 3;
    const int wm0 = (wid % WARPS_M) * WM;
    const int wn0 = (wid / WARPS_M) * WN;

    float acc[MT][NTL][4];
    #pragma unroll
    for (int i = 0; i < MT; i++)
        #pragma unroll
        for (int j = 0; j < NTL; j++)
            #pragma unroll
            for (int q = 0; q < 4; q++) acc[i][j][q] = 0.0f;

    auto load_stage = [&](int s, int kk) {
        #pragma unroll
        for (int j = 0; j < LDA; j++) {
            int i = tid + j * NT;
            int r = i / (BK / 4), c4 = i % (BK / 4);
            cp_async16((uint32_t)__cvta_generic_to_shared(&As[s * ASZ + r * ASTR + c4 * 4]),
                       A + (size_t)(bm + r) * K + kk + c4 * 4);
        }
        #pragma unroll
        for (int j = 0; j < LDB; j++) {
            int i = tid + j * NT;
            int r = i / (BN / 4), c4 = i % (BN / 4);
            cp_async16((uint32_t)__cvta_generic_to_shared(&Bs[s * BSZ + r * BSTR + c4 * 4]),
                       Bw + (size_t)(kk + r) * N + bn + c4 * 4);
        }
        asm volatile("cp.async.commit_group;\n" ::: "memory");
    };

    const int nk = Ksplit / BK;
    load_stage(0, k0);
    int s = 0;
    for (int kk = 0; kk < nk; kk++) {
        if (kk + 1 < nk) {
            load_stage(s ^ 1, k0 + (kk + 1) * BK);
            asm volatile("cp.async.wait_group 1;\n" ::: "memory");
        } else {
            asm volatile("cp.async.wait_group 0;\n" ::: "memory");
        }
        __syncthreads();

        #pragma unroll
        for (int k8 = 0; k8 < BK / 8; k8++) {
            uint32_t af[MT][4];
            uint32_t bf[NTL][2];
            #pragma unroll
            for (int mt = 0; mt < MT; mt++) {
                const uint32_t* p = (const uint32_t*)
                    &As[s * ASZ + (wm0 + mt * 16 + gid) * ASTR + k8 * 8 + tig];
                af[mt][0] = p[0];
                af[mt][1] = p[8 * ASTR];
                af[mt][2] = p[4];
                af[mt][3] = p[8 * ASTR + 4];
            }
            #pragma unroll
            for (int nt = 0; nt < NTL; nt++) {
                const uint32_t* p = (const uint32_t*)
                    &Bs[s * BSZ + (k8 * 8 + tig) * BSTR + wn0 + nt * 8 + gid];
                bf[nt][0] = p[0];
                bf[nt][1] = p[4 * BSTR];
            }
            #pragma unroll
            for (int mt = 0; mt < MT; mt++)
                #pragma unroll
                for (int nt = 0; nt < NTL; nt++)
                    mma_tf32(acc[mt][nt], af[mt], bf[nt]);
        }
        __syncthreads();
        s ^= 1;
    }

    // Epilogue: (bias +ReLU) unless SPLITK partial; optional tf32 rounding.
    #pragma unroll
    for (int mt = 0; mt < MT; mt++) {
        const int m0 = bm + wm0 + mt * 16 + gid;
        #pragma unroll
        for (int nt = 0; nt < NTL; nt++) {
            const int n0 = bn + wn0 + nt * 8 + 2 * tig;
            float bv0 = 0.0f, bv1 = 0.0f;
            if (!SPLITK) { bv0 = bias[n0]; bv1 = bias[n0 + 1]; }
            float v0 = acc[mt][nt][0] + bv0;
            float v1 = acc[mt][nt][1] + bv1;
            float v2 = acc[mt][nt][2] + bv0;
            float v3 = acc[mt][nt][3] + bv1;
            if (RELU) {
                v0 = fmaxf(v0, 0.0f); v1 = fmaxf(v1, 0.0f);
                v2 = fmaxf(v2, 0.0f); v3 = fmaxf(v3, 0.0f);
            }
            if (ROUND_OUT) {
                v0 = tf32r(v0); v1 = tf32r(v1); v2 = tf32r(v2); v3 = tf32r(v3);
            }
            *(float2*)(C + (size_t)m0 * N + n0)       = make_float2(v0, v1);
            *(float2*)(C + (size_t)(m0 + 8) * N + n0) = make_float2(v2, v3);
        }
    }
}

// ---------------------------------------------------------------------------
// Split-K reduce: out = sum_s part[s] + bias   (fixed order -> deterministic)
// ---------------------------------------------------------------------------
__global__ void k_reduce(const float* __restrict__ part,
                         const float* __restrict__ bias,
                         float* __restrict__ out) {
    const size_t i4 = (size_t)blockIdx.x * blockDim.x + threadIdx.x;
    const size_t e = i4 * 4;
    const int n0 = (int)(e & (H_ - 1));
    float4 b = *(const float4*)(bias + n0);
    float4 r = make_float4(b.x, b.y, b.z, b.w);
    #pragma unroll
    for (int s = 0; s < KSPLIT; s++) {
        float4 a = *(const float4*)(part + (size_t)s * MN + e);
        r.x += a.x; r.y += a.y; r.z += a.z; r.w += a.w;
    }
    *(float4*)(out + e) = r;
}

// ---------------------------------------------------------------------------
// Input order per setup_inputs dict:
//  0 token_reps f32 (B,S,H)      1 token_masks bool (B,S)   2 span_reps f32 (B,NS,H)
//  3 span_ids  i32 (B,NS,2)      4 rel_ids   i32 (B,NR,2)   5 rel_masks bool (B,NR)
//  6 neg_limit f32 scalar        7 W1 (768,3072)  8 b1 (3072,)
//  9 W2 (3072,256)              10 b2 (256,)
// Output: f32 (B, NR, H) = 524288 (2*512*256)
// ---------------------------------------------------------------------------
extern "C" void kernel_launch(void* const* d_in, const int* in_sizes, int n_in,
                              void* d_out, int out_size) {
    const float* tok   = (const float*)d_in[0];
    const float* spans = (const float*)d_in[2];
    const int*   sids  = (const int*)d_in[3];
    const int*   rids  = (const int*)d_in[4];
    const float* negp  = (const float*)d_in[6];
    const float* W1    = (const float*)d_in[7];
    const float* b1    = (const float*)d_in[8];
    const float* W2    = (const float*)d_in[9];
    const float* b2    = (const float*)d_in[10];
    float* out = (float*)d_out;

    float *rel, *hbuf, *part, *w1r, *w2r;
    cudaGetSymbolAddress((void**)&rel,  g_rel);
    cudaGetSymbolAddress((void**)&hbuf, g_h);
    cudaGetSymbolAddress((void**)&part, g_part);
    cudaGetSymbolAddress((void**)&w1r,  g_w1r);
    cudaGetSymbolAddress((void**)&w2r,  g_w2r);

    // GEMM1 (R12-proven): 128x64x32 tiles, 8 warps of 32x32
    constexpr int GSMEM1 = (2 * (128 * 36) + 2 * (32 * 72)) * 4;    // 55296
    // GEMM2 (new): 128x128x32 tiles, 8 warps of 32x64
    constexpr int GSMEM2 = (2 * (128 * 36) + 2 * (32 * 136)) * 4;   // 71680
    cudaFuncSetAttribute(k_tgemm<128, 64, 32, 32, 32, true, false, true>,
                         cudaFuncAttributeMaxDynamicSharedMemorySize, GSMEM1);
    cudaFuncSetAttribute(k_tgemm<128, 128, 32, 32, 64, false, true, false>,
                         cudaFuncAttributeMaxDynamicSharedMemorySize, GSMEM2);

    // Pre-round both weight matrices to tf32 in one launch
    constexpr size_t N1 = (size_t)DIN * DFF;
    constexpr size_t N2 = (size_t)DFF * H_;
    k_round<<<(int)((N1 + N2) / 4 / 256), 256>>>(W1, w1r, N1, W2, w2r);

    // Pooling scan tables (replace plain block-max kernels)
    k_scan<<<B_ * NBLK, H_>>>(tok);
    k_scanF<<<B_ * NCBLK, H_>>>();
    k_rel<<<B_ * NR_, H_>>>(tok, spans, sids, rids, negp);

    // GEMM1: (2048 x 768) @ (768 x 3072) + b1, ReLU -> 768 CTAs (R12 config)
    k_tgemm<128, 64, 32, 32, 32, true, false, true>
        <<<dim3(DFF / 64, (B_ * NR_) / 128), 256, GSMEM1>>>(rel, w1r, b1, hbuf,
                                                            B_ * NR_, DFF, DIN, DIN);
    // GEMM2: (2048 x 3072) @ (3072 x 256), split-K=12 -> 384 CTAs, BN=128
    k_tgemm<128, 128, 32, 32, 64, false, true, false>
        <<<dim3(H_ / 128, (B_ * NR_) / 128, KSPLIT), 256, GSMEM2>>>(hbuf, w2r, nullptr,
                                                                    part, B_ * NR_, H_,
                                                                    DFF, DFF / KSPLIT);
    // Reduce partials + bias -> out
    k_reduce<<<(int)(MN / 4 / 256), 256>>>(part, b2, out);
}

// round 16
// speedup vs baseline: 1.0270x; 1.0270x over previous
#include <cuda_runtime.h>
#include <cstdint>
#include <cstddef>

// Problem constants (fixed by the reference's setup_inputs)
#define B_   2
#define S_   2048
#define H_   256
#define NS_  512
#define NR_  512
#define DIN  768    // 3*H
#define DFF  3072   // 4*DIN
#define NBLK (S_ / 16)    // 128 fine (16-token) blocks per batch row
#define NCBLK (S_ / 256)  // 8 coarse (256-token) blocks per batch row
#define KSPLIT 8
#define MN   ((size_t)B_ * NR_ * H_)     // 524288 output elems

// Scratch (static device globals: allocation-free per harness rules)
__device__ float g_ctx[(size_t)B_ * NR_ * H_];         // 2 MB   context reps (tf32-rounded)
__device__ float g_sr[(size_t)B_ * NS_ * H_];          // 1 MB   span_reps tf32-rounded
__device__ int   g_hti[(size_t)B_ * NR_ * 2];          // 8 KB   per-relation span rows
__device__ float g_h[(size_t)B_ * NR_ * DFF];          // 24 MB  hidden (tf32-rounded)
__device__ float g_blkmax[(size_t)B_ * NBLK * H_];     // 256 KB fine block maxima
__device__ float g_blkmax2[(size_t)B_ * NCBLK * H_];   // 16 KB  coarse block maxima
__device__ float g_part[(size_t)KSPLIT * MN];          // 16 MB  split-K partials
__device__ float g_w1r[(size_t)DIN * DFF];             // 9.4 MB W1 tf32-rounded
__device__ float g_w2r[(size_t)DFF * H_];              // 3 MB   W2 tf32-rounded

__device__ __forceinline__ uint32_t f2tf32(float f) {
    uint32_t r;
    asm("cvt.rna.tf32.f32 %0, %1;" : "=r"(r) : "f"(f));
    return r;
}
__device__ __forceinline__ float tf32r(float f) { return __uint_as_float(f2tf32(f)); }

// ---------------------------------------------------------------------------
// Pre-round W1, W2, span_reps to tf32 in one launch (float4 vectorized).
// ---------------------------------------------------------------------------
__global__ void k_round(const float* __restrict__ in1, float* __restrict__ out1,
                        size_t n1,
                        const float* __restrict__ in2, float* __restrict__ out2,
                        size_t n2,
                        const float* __restrict__ in3, float* __restrict__ out3) {
    size_t i = ((size_t)blockIdx.x * blockDim.x + threadIdx.x) * 4;
    const float* in = in1;
    float* out = out1;
    if (i >= n1) {
        i -= n1;
        if (i >= n2) { i -= n2; in = in3; out = out3; }
        else         { in = in2; out = out2; }
    }
    float4 v = *(const float4*)(in + i);
    v.x = tf32r(v.x); v.y = tf32r(v.y); v.z = tf32r(v.z); v.w = tf32r(v.w);
    *(float4*)(out + i) = v;
}

// ---------------------------------------------------------------------------
// Kernel 0: per-16-token (fine) block maxima of token_reps (R12-proven).
// ---------------------------------------------------------------------------
__global__ void k_blkmax(const float* __restrict__ tok,
                         const float* __restrict__ negp) {
    const int blk = blockIdx.x;
    const int h = threadIdx.x;
    float m = *negp;
    const float* p = tok + (size_t)blk * 16 * H_ + h;
    #pragma unroll
    for (int i = 0; i < 16; i++) m = fmaxf(m, p[(size_t)i * H_]);
    g_blkmax[(size_t)blk * H_ + h] = m;
}

// ---------------------------------------------------------------------------
// Kernel 0b: coarse (256-token) block maxima = max over 16 fine blocks.
// ---------------------------------------------------------------------------
__global__ void k_blkmax2(void) {
    const int cb = blockIdx.x;
    const int h = threadIdx.x;
    const float* p = g_blkmax + (size_t)cb * 16 * H_ + h;
    float m = p[0];
    #pragma unroll
    for (int i = 1; i < 16; i++) m = fmaxf(m, p[(size_t)i * H_]);
    g_blkmax2[(size_t)cb * H_ + h] = m;
}

// ---------------------------------------------------------------------------
// Kernel 1: context max-pool ONLY (head/tail gather is fused into GEMM1).
// Writes g_ctx[br] (tf32-rounded) and g_hti[br] = global span rows.
// Two-level block maxima (R12-proven segment walk).
// ---------------------------------------------------------------------------
__global__ void __launch_bounds__(256)
k_rel(const float* __restrict__ tok,
      const int* __restrict__ span_ids,
      const int* __restrict__ rel_ids,
      const float* __restrict__ negp) {
    const int br = blockIdx.x;           // b*NR + r
    const int b = br >> 9;
    const int h = threadIdx.x;
    const float neg = *negp;

    const int head = rel_ids[br * 2 + 0];
    const int tail = rel_ids[br * 2 + 1];
    const int sb = b * NS_;
    if (h < 2) g_hti[br * 2 + h] = sb + (h ? tail : head);

    const int hs = span_ids[(sb + head) * 2 + 0];
    const int he = span_ids[(sb + head) * 2 + 1];
    const int ts = span_ids[(sb + tail) * 2 + 0];
    const int te = span_ids[(sb + tail) * 2 + 1];

    const int lo = min(he, te);
    const int hi = max(hs, ts);

    int s1 = min(max(hs, lo), hi), e1 = min(max(he, lo), hi);
    int s2 = min(max(ts, lo), hi), e2 = min(max(te, lo), hi);
    if (s2 < s1) { int t = s1; s1 = s2; s2 = t; t = e1; e1 = e2; e2 = t; }
    if (s2 < e1) { e1 = max(e1, e2); s2 = e1; e2 = e1; }

    const float* tb  = tok + (size_t)b * S_ * H_ + h;
    const float* bb  = g_blkmax + (size_t)b * NBLK * H_ + h;
    const float* cbb = g_blkmax2 + (size_t)b * NCBLK * H_ + h;
    float m = neg;

    const int seg_a[3] = { lo, e1, e2 };
    const int seg_b[3] = { s1, s2, hi };
    #pragma unroll
    for (int s = 0; s < 3; s++) {
        const int a = seg_a[s], bnd = seg_b[s];
        if (a >= bnd) continue;
        int a16 = (a + 15) & ~15;
        int b16 = bnd & ~15;
        if (a16 >= b16) {
            for (int t = a; t < bnd; t++) m = fmaxf(m, tb[(size_t)t * H_]);
            continue;
        }
        for (int t = a; t < a16; t++) m = fmaxf(m, tb[(size_t)t * H_]);
        const int j0 = a16 >> 4, j1 = b16 >> 4;
        const int jc0 = (j0 + 15) & ~15;
        const int jc1 = j1 & ~15;
        if (jc0 >= jc1) {
            for (int j = j0; j < j1; j++) m = fmaxf(m, bb[(size_t)j * H_]);
        } else {
            for (int j = j0; j < jc0; j++) m = fmaxf(m, bb[(size_t)j * H_]);
            for (int c = (jc0 >> 4); c < (jc1 >> 4); c++)
                m = fmaxf(m, cbb[(size_t)c * H_]);
            for (int j = jc1; j < j1; j++) m = fmaxf(m, bb[(size_t)j * H_]);
        }
        for (int t = b16; t < bnd; t++) m = fmaxf(m, tb[(size_t)t * H_]);
    }

    const int allneg = __syncthreads_and(m == neg);
    g_ctx[(size_t)br * H_ + h] = allneg ? 0.0f : tf32r(m);
}

// ---------------------------------------------------------------------------
// Shared GEMM helpers.
// ---------------------------------------------------------------------------
__device__ __forceinline__ void cp_async16(uint32_t dst, const void* src) {
    asm volatile("cp.async.cg.shared.global [%0], [%1], 16;\n"
                 :: "r"(dst), "l"(src));
}

__device__ __forceinline__ void mma_tf32(float* c, const uint32_t* a, const uint32_t* b) {
    asm volatile(
        "mma.sync.aligned.m16n8k8.row.col.f32.tf32.tf32.f32 "
        "{%0,%1,%2,%3}, {%4,%5,%6,%7}, {%8,%9}, {%0,%1,%2,%3};"
        : "+f"(c[0]), "+f"(c[1]), "+f"(c[2]), "+f"(c[3])
        : "r"(a[0]), "r"(a[1]), "r"(a[2]), "r"(a[3]), "r"(b[0]), "r"(b[1]));
}

// ---------------------------------------------------------------------------
// GEMM1 with FUSED GATHER: A row m = [spans_r[hid[m]] | spans_r[tid[m]] | ctx[m]].
// Each BK=32 tile lies entirely in one section (256 % 32 == 0), so the source
// pointer is section-selected per stage. Row ids loaded ONCE per thread.
// BM=128, BN=64, BK=32, 8 warps of 32x32 (R12-proven shape), ReLU + tf32-round.
// ---------------------------------------------------------------------------
__global__ void __launch_bounds__(256)
k_gemm1(const float* __restrict__ sr, const float* __restrict__ ctx,
        const int* __restrict__ hti, const float* __restrict__ Bw,
        const float* __restrict__ bias, float* __restrict__ C) {
    constexpr int BM = 128, BN = 64, BK = 32, WM = 32, WN = 32;
    constexpr int WARPS_M = BM / WM;                 // 4
    constexpr int ASTR = BK + 4, BSTR = BN + 8;
    constexpr int MT = WM / 16, NTL = WN / 8;        // 2, 4
    constexpr int ASZ = BM * ASTR, BSZ = BK * BSTR;

    extern __shared__ float dsm[];
    float* As = dsm;
    float* Bs = dsm + 2 * ASZ;

    const int tid = threadIdx.x;
    const int bm = blockIdx.y * BM;
    const int bn = blockIdx.x * BN;
    const int wid = tid >> 5, lane = tid & 31;
    const int gid = lane >> 2, tig = lane & 3;
    const int wm0 = (wid % WARPS_M) * WM;
    const int wn0 = (wid / WARPS_M) * WN;

    // Per-thread A-load coordinates: 4 fixed rows, one 16B chunk each.
    const int r0 = tid >> 3;            // 0..31
    const int ac4 = (tid & 7) * 4;      // 0,4,..,28
    int hid[4], tid_[4];
    #pragma unroll
    for (int j = 0; j < 4; j++) {
        const int r = bm + r0 + j * 32;
        hid[j]  = hti[r * 2 + 0];
        tid_[j] = hti[r * 2 + 1];
    }

    float acc[MT][NTL][4];
    #pragma unroll
    for (int i = 0; i < MT; i++)
        #pragma unroll
        for (int j = 0; j < NTL; j++)
            #pragma unroll
            for (int q = 0; q < 4; q++) acc[i][j][q] = 0.0f;

    auto load_stage = [&](int s, int kk) {
        const int sec = kk >> 8;
        const int ko = (kk & 255) + ac4;
        #pragma unroll
        for (int j = 0; j < 4; j++) {
            const int r = r0 + j * 32;
            const float* src =
                (sec == 0) ? sr + (size_t)hid[j] * H_ + ko :
                (sec == 1) ? sr + (size_t)tid_[j] * H_ + ko :
                             ctx + (size_t)(bm + r) * H_ + ko;
            cp_async16((uint32_t)__cvta_generic_to_shared(&As[s * ASZ + r * ASTR + ac4]),
                       src);
        }
        #pragma unroll
        for (int j = 0; j < 2; j++) {    // B: 32 rows x 64 floats
            int i = tid + j * 256;
            int r = i >> 4, c4 = (i & 15) * 4;
            cp_async16((uint32_t)__cvta_generic_to_shared(&Bs[s * BSZ + r * BSTR + c4]),
                       Bw + (size_t)(kk + r) * DFF + bn + c4);
        }
        asm volatile("cp.async.commit_group;\n" ::: "memory");
    };

    constexpr int nk = DIN / BK;        // 24
    load_stage(0, 0);
    int s = 0;
    for (int kk = 0; kk < nk; kk++) {
        if (kk + 1 < nk) {
            load_stage(s ^ 1, (kk + 1) * BK);
            asm volatile("cp.async.wait_group 1;\n" ::: "memory");
        } else {
            asm volatile("cp.async.wait_group 0;\n" ::: "memory");
        }
        __syncthreads();

        #pragma unroll
        for (int k8 = 0; k8 < BK / 8; k8++) {
            uint32_t af[MT][4];
            uint32_t bf[NTL][2];
            #pragma unroll
            for (int mt = 0; mt < MT; mt++) {
                const uint32_t* p = (const uint32_t*)
                    &As[s * ASZ + (wm0 + mt * 16 + gid) * ASTR + k8 * 8 + tig];
                af[mt][0] = p[0];
                af[mt][1] = p[8 * ASTR];
                af[mt][2] = p[4];
                af[mt][3] = p[8 * ASTR + 4];
            }
            #pragma unroll
            for (int nt = 0; nt < NTL; nt++) {
                const uint32_t* p = (const uint32_t*)
                    &Bs[s * BSZ + (k8 * 8 + tig) * BSTR + wn0 + nt * 8 + gid];
                bf[nt][0] = p[0];
                bf[nt][1] = p[4 * BSTR];
            }
            #pragma unroll
            for (int mt = 0; mt < MT; mt++)
                #pragma unroll
                for (int nt = 0; nt < NTL; nt++)
                    mma_tf32(acc[mt][nt], af[mt], bf[nt]);
        }
        __syncthreads();
        s ^= 1;
    }

    #pragma unroll
    for (int mt = 0; mt < MT; mt++) {
        const int m0 = bm + wm0 + mt * 16 + gid;
        #pragma unroll
        for (int nt = 0; nt < NTL; nt++) {
            const int n0 = bn + wn0 + nt * 8 + 2 * tig;
            const float bv0 = bias[n0], bv1 = bias[n0 + 1];
            float v0 = tf32r(fmaxf(acc[mt][nt][0] + bv0, 0.0f));
            float v1 = tf32r(fmaxf(acc[mt][nt][1] + bv1, 0.0f));
            float v2 = tf32r(fmaxf(acc[mt][nt][2] + bv0, 0.0f));
            float v3 = tf32r(fmaxf(acc[mt][nt][3] + bv1, 0.0f));
            *(float2*)(C + (size_t)m0 * DFF + n0)       = make_float2(v0, v1);
            *(float2*)(C + (size_t)(m0 + 8) * DFF + n0) = make_float2(v2, v3);
        }
    }
}

// ---------------------------------------------------------------------------
// GEMM2: legacy tf32 split-K (R12-proven config, unchanged).
// ---------------------------------------------------------------------------
template <int BM, int BN, int BK, int WM, int WN>
__global__ void __launch_bounds__((BM / WM) * (BN / WN) * 32)
k_tgemm2(const float* __restrict__ A, const float* __restrict__ Bw,
         float* __restrict__ C, int M, int N, int K, int Ksplit) {
    constexpr int WARPS_M = BM / WM;
    constexpr int WARPS_N = BN / WN;
    constexpr int NT = WARPS_M * WARPS_N * 32;
    constexpr int ASTR = BK + 4;
    constexpr int BSTR = BN + 8;
    constexpr int MT = WM / 16;
    constexpr int NTL = WN / 8;
    constexpr int LDA = (BM * BK / 4) / NT;
    constexpr int LDB = (BK * BN / 4) / NT;
    constexpr int ASZ = BM * ASTR;
    constexpr int BSZ = BK * BSTR;

    extern __shared__ float dsm[];
    float* As = dsm;
    float* Bs = dsm + 2 * ASZ;

    const int tid = threadIdx.x;
    const int bm = blockIdx.y * BM;
    const int bn = blockIdx.x * BN;
    const int k0 = blockIdx.z * Ksplit;
    C += (size_t)blockIdx.z * M * N;
    const int wid = tid >> 5, lane = tid & 31;
    const int gid = lane >> 2, tig = lane & 3;
    const int wm0 = (wid % WARPS_M) * WM;
    const int wn0 = (wid / WARPS_M) * WN;

    float acc[MT][NTL][4];
    #pragma unroll
    for (int i = 0; i < MT; i++)
        #pragma unroll
        for (int j = 0; j < NTL; j++)
            #pragma unroll
            for (int q = 0; q < 4; q++) acc[i][j][q] = 0.0f;

    auto load_stage = [&](int s, int kk) {
        #pragma unroll
        for (int j = 0; j < LDA; j++) {
            int i = tid + j * NT;
            int r = i / (BK / 4), c4 = i % (BK / 4);
            cp_async16((uint32_t)__cvta_generic_to_shared(&As[s * ASZ + r * ASTR + c4 * 4]),
                       A + (size_t)(bm + r) * K + kk + c4 * 4);
        }
        #pragma unroll
        for (int j = 0; j < LDB; j++) {
            int i = tid + j * NT;
            int r = i / (BN / 4), c4 = i % (BN / 4);
            cp_async16((uint32_t)__cvta_generic_to_shared(&Bs[s * BSZ + r * BSTR + c4 * 4]),
                       Bw + (size_t)(kk + r) * N + bn + c4 * 4);
        }
        asm volatile("cp.async.commit_group;\n" ::: "memory");
    };

    const int nk = Ksplit / BK;
    load_stage(0, k0);
    int s = 0;
    for (int kk = 0; kk < nk; kk++) {
        if (kk + 1 < nk) {
            load_stage(s ^ 1, k0 + (kk + 1) * BK);
            asm volatile("cp.async.wait_group 1;\n" ::: "memory");
        } else {
            asm volatile("cp.async.wait_group 0;\n" ::: "memory");
        }
        __syncthreads();

        #pragma unroll
        for (int k8 = 0; k8 < BK / 8; k8++) {
            uint32_t af[MT][4];
            uint32_t bf[NTL][2];
            #pragma unroll
            for (int mt = 0; mt < MT; mt++) {
                const uint32_t* p = (const uint32_t*)
                    &As[s * ASZ + (wm0 + mt * 16 + gid) * ASTR + k8 * 8 + tig];
                af[mt][0] = p[0];
                af[mt][1] = p[8 * ASTR];
                af[mt][2] = p[4];
                af[mt][3] = p[8 * ASTR + 4];
            }
            #pragma unroll
            for (int nt = 0; nt < NTL; nt++) {
                const uint32_t* p = (const uint32_t*)
                    &Bs[s * BSZ + (k8 * 8 + tig) * BSTR + wn0 + nt * 8 + gid];
                bf[nt][0] = p[0];
                bf[nt][1] = p[4 * BSTR];
            }
            #pragma unroll
            for (int mt = 0; mt < MT; mt++)
                #pragma unroll
                for (int nt = 0; nt < NTL; nt++)
                    mma_tf32(acc[mt][nt], af[mt], bf[nt]);
        }
        __syncthreads();
        s ^= 1;
    }

    #pragma unroll
    for (int mt = 0; mt < MT; mt++) {
        const int m0 = bm + wm0 + mt * 16 + gid;
        #pragma unroll
        for (int nt = 0; nt < NTL; nt++) {
            const int n0 = bn + wn0 + nt * 8 + 2 * tig;
            *(float2*)(C + (size_t)m0 * N + n0) =
                make_float2(acc[mt][nt][0], acc[mt][nt][1]);
            *(float2*)(C + (size_t)(m0 + 8) * N + n0) =
                make_float2(acc[mt][nt][2], acc[mt][nt][3]);
        }
    }
}

// ---------------------------------------------------------------------------
// Split-K reduce: out = sum_s part[s] + bias   (fixed order -> deterministic)
// ---------------------------------------------------------------------------
__global__ void k_reduce(const float* __restrict__ part,
                         const float* __restrict__ bias,
                         float* __restrict__ out) {
    const size_t i4 = (size_t)blockIdx.x * blockDim.x + threadIdx.x;
    const size_t e = i4 * 4;
    const int n0 = (int)(e & (H_ - 1));
    float4 b = *(const float4*)(bias + n0);
    float4 r = make_float4(b.x, b.y, b.z, b.w);
    #pragma unroll
    for (int s = 0; s < KSPLIT; s++) {
        float4 a = *(const float4*)(part + (size_t)s * MN + e);
        r.x += a.x; r.y += a.y; r.z += a.z; r.w += a.w;
    }
    *(float4*)(out + e) = r;
}

// ---------------------------------------------------------------------------
// Input order per setup_inputs dict:
//  0 token_reps f32 (B,S,H)      1 token_masks bool (B,S)   2 span_reps f32 (B,NS,H)
//  3 span_ids  i32 (B,NS,2)      4 rel_ids   i32 (B,NR,2)   5 rel_masks bool (B,NR)
//  6 neg_limit f32 scalar        7 W1 (768,3072)  8 b1 (3072,)
//  9 W2 (3072,256)              10 b2 (256,)
// Output: f32 (B, NR, H) = 524288 (2*512*256)
// ---------------------------------------------------------------------------
extern "C" void kernel_launch(void* const* d_in, const int* in_sizes, int n_in,
                              void* d_out, int out_size) {
    const float* tok   = (const float*)d_in[0];
    const float* spans = (const float*)d_in[2];
    const int*   sids  = (const int*)d_in[3];
    const int*   rids  = (const int*)d_in[4];
    const float* negp  = (const float*)d_in[6];
    const float* W1    = (const float*)d_in[7];
    const float* b1    = (const float*)d_in[8];
    const float* W2    = (const float*)d_in[9];
    const float* b2    = (const float*)d_in[10];
    float* out = (float*)d_out;

    float *ctx, *sr, *hbuf, *part, *w1r, *w2r;
    int* hti;
    cudaGetSymbolAddress((void**)&ctx,  g_ctx);
    cudaGetSymbolAddress((void**)&sr,   g_sr);
    cudaGetSymbolAddress((void**)&hti,  g_hti);
    cudaGetSymbolAddress((void**)&hbuf, g_h);
    cudaGetSymbolAddress((void**)&part, g_part);
    cudaGetSymbolAddress((void**)&w1r,  g_w1r);
    cudaGetSymbolAddress((void**)&w2r,  g_w2r);

    // Both GEMMs use the same smem budget (R12-proven tile shape)
    constexpr int GSMEM = (2 * (128 * 36) + 2 * (32 * 72)) * 4;   // 55296
    cudaFuncSetAttribute(k_gemm1, cudaFuncAttributeMaxDynamicSharedMemorySize, GSMEM);
    cudaFuncSetAttribute(k_tgemm2<128, 64, 32, 32, 32>,
                         cudaFuncAttributeMaxDynamicSharedMemorySize, GSMEM);

    // Pre-round W1, W2, span_reps to tf32 (one launch)
    constexpr size_t N1 = (size_t)DIN * DFF;
    constexpr size_t N2 = (size_t)DFF * H_;
    constexpr size_t N3 = (size_t)B_ * NS_ * H_;
    k_round<<<(int)((N1 + N2 + N3) / 4 / 256), 256>>>(W1, w1r, N1, W2, w2r, N2,
                                                      spans, sr);

    k_blkmax<<<B_ * NBLK, H_>>>(tok, negp);
    k_blkmax2<<<B_ * NCBLK, H_>>>();
    k_rel<<<B_ * NR_, H_>>>(tok, sids, rids, negp);

    // GEMM1 (fused gather): relu([sr[h]|sr[t]|ctx] @ W1 + b1) -> 768 CTAs
    k_gemm1<<<dim3(DFF / 64, (B_ * NR_) / 128), 256, GSMEM>>>(sr, ctx, hti,
                                                              w1r, b1, hbuf);
    // GEMM2: (2048 x 3072) @ (3072 x 256), split-K=8 -> 512 CTAs (R12 config)
    k_tgemm2<128, 64, 32, 32, 32>
        <<<dim3(H_ / 64, (B_ * NR_) / 128, KSPLIT), 256, GSMEM>>>(hbuf, w2r, part,
                                                                  B_ * NR_, H_,
                                                                  DFF, DFF / KSPLIT);
    // Reduce partials + bias -> out
    k_reduce<<<(int)(MN / 4 / 256), 256>>>(part, b2, out);
}

// round 17
// speedup vs baseline: 1.0832x; 1.0548x over previous
#include <cuda_runtime.h>
#include <cstdint>
#include <cstddef>

// Problem constants (fixed by the reference's setup_inputs)
#define B_   2
#define S_   2048
#define H_   256
#define NS_  512
#define NR_  512
#define DIN  768    // 3*H
#define DFF  3072   // 4*DIN
#define NBLK (S_ / 16)    // 128 fine (16-token) blocks per batch row
#define NCBLK (S_ / 256)  // 8 coarse (256-token) blocks per batch row
#define KSPLIT 8
#define MN   ((size_t)B_ * NR_ * H_)     // 524288 output elems

// Front-kernel block partition
#define NB_ROUND 3328     // (768*3072 + 3072*256 + 2*512*256) / 4 / 256
#define NB_BMAX  (B_ * NBLK)          // 256
#define NB_OINIT ((int)(MN / 4 / 256)) // 512

// Scratch (static device globals: allocation-free per harness rules)
__device__ float g_ctx[(size_t)B_ * NR_ * H_];         // 2 MB   context reps (tf32-rounded)
__device__ float g_sr[(size_t)B_ * NS_ * H_];          // 1 MB   span_reps tf32-rounded
__device__ int   g_hti[(size_t)B_ * NR_ * 2];          // 8 KB   per-relation span rows
__device__ float g_h[(size_t)B_ * NR_ * DFF];          // 24 MB  hidden (tf32-rounded)
__device__ float g_blkmax[(size_t)B_ * NBLK * H_];     // 256 KB fine block maxima
__device__ float g_blkmax2[(size_t)B_ * NCBLK * H_];   // 16 KB  coarse block maxima
__device__ float g_w1r[(size_t)DIN * DFF];             // 9.4 MB W1 tf32-rounded
__device__ float g_w2r[(size_t)DFF * H_];              // 3 MB   W2 tf32-rounded

__device__ __forceinline__ uint32_t f2tf32(float f) {
    uint32_t r;
    asm("cvt.rna.tf32.f32 %0, %1;" : "=r"(r) : "f"(f));
    return r;
}
__device__ __forceinline__ float tf32r(float f) { return __uint_as_float(f2tf32(f)); }

// ---------------------------------------------------------------------------
// Front kernel: three independent jobs partitioned by blockIdx.x —
//   [0, NB_ROUND):          tf32-round W1, W2, span_reps (float4)
//   [NB_ROUND, +NB_BMAX):   per-16-token fine block maxima of token_reps
//   [.., +NB_OINIT):        out = bias2 (atomic split-K accumulates on top)
// Merging removes 2 launch gaps and fills the chip during the small phase.
// ---------------------------------------------------------------------------
__global__ void __launch_bounds__(256)
k_front(const float* __restrict__ W1, float* __restrict__ w1r,
        const float* __restrict__ W2, float* __restrict__ w2r,
        const float* __restrict__ spans, float* __restrict__ sr,
        const float* __restrict__ tok, const float* __restrict__ negp,
        const float* __restrict__ b2, float* __restrict__ out) {
    const int blk = blockIdx.x;
    if (blk < NB_ROUND) {
        constexpr size_t N1 = (size_t)DIN * DFF;
        constexpr size_t N2 = (size_t)DFF * H_;
        size_t i = ((size_t)blk * 256 + threadIdx.x) * 4;
        const float* in = W1;
        float* o = w1r;
        if (i >= N1) {
            i -= N1;
            if (i >= N2) { i -= N2; in = spans; o = sr; }
            else         { in = W2; o = w2r; }
        }
        float4 v = *(const float4*)(in + i);
        v.x = tf32r(v.x); v.y = tf32r(v.y); v.z = tf32r(v.z); v.w = tf32r(v.w);
        *(float4*)(o + i) = v;
    } else if (blk < NB_ROUND + NB_BMAX) {
        const int bb = blk - NB_ROUND;
        const int h = threadIdx.x;
        float m = *negp;
        const float* p = tok + (size_t)bb * 16 * H_ + h;
        #pragma unroll
        for (int i = 0; i < 16; i++) m = fmaxf(m, p[(size_t)i * H_]);
        g_blkmax[(size_t)bb * H_ + h] = m;
    } else {
        const int ob = blk - NB_ROUND - NB_BMAX;
        const size_t e = ((size_t)ob * 256 + threadIdx.x) * 4;
        const int n0 = (int)(e & (H_ - 1));
        *(float4*)(out + e) = *(const float4*)(b2 + n0);
    }
}

// ---------------------------------------------------------------------------
// Kernel 0b: coarse (256-token) block maxima = max over 16 fine blocks.
// ---------------------------------------------------------------------------
__global__ void k_blkmax2(void) {
    const int cb = blockIdx.x;
    const int h = threadIdx.x;
    const float* p = g_blkmax + (size_t)cb * 16 * H_ + h;
    float m = p[0];
    #pragma unroll
    for (int i = 1; i < 16; i++) m = fmaxf(m, p[(size_t)i * H_]);
    g_blkmax2[(size_t)cb * H_ + h] = m;
}

// ---------------------------------------------------------------------------
// Kernel 1: context max-pool ONLY (head/tail gather fused into GEMM1).
// Writes g_ctx[br] (tf32-rounded) and g_hti[br] = global span rows.
// Two-level block maxima (R12-proven segment walk).
// ---------------------------------------------------------------------------
__global__ void __launch_bounds__(256)
k_rel(const float* __restrict__ tok,
      const int* __restrict__ span_ids,
      const int* __restrict__ rel_ids,
      const float* __restrict__ negp) {
    const int br = blockIdx.x;           // b*NR + r
    const int b = br >> 9;
    const int h = threadIdx.x;
    const float neg = *negp;

    const int head = rel_ids[br * 2 + 0];
    const int tail = rel_ids[br * 2 + 1];
    const int sb = b * NS_;
    if (h < 2) g_hti[br * 2 + h] = sb + (h ? tail : head);

    const int hs = span_ids[(sb + head) * 2 + 0];
    const int he = span_ids[(sb + head) * 2 + 1];
    const int ts = span_ids[(sb + tail) * 2 + 0];
    const int te = span_ids[(sb + tail) * 2 + 1];

    const int lo = min(he, te);
    const int hi = max(hs, ts);

    int s1 = min(max(hs, lo), hi), e1 = min(max(he, lo), hi);
    int s2 = min(max(ts, lo), hi), e2 = min(max(te, lo), hi);
    if (s2 < s1) { int t = s1; s1 = s2; s2 = t; t = e1; e1 = e2; e2 = t; }
    if (s2 < e1) { e1 = max(e1, e2); s2 = e1; e2 = e1; }

    const float* tb  = tok + (size_t)b * S_ * H_ + h;
    const float* bb  = g_blkmax + (size_t)b * NBLK * H_ + h;
    const float* cbb = g_blkmax2 + (size_t)b * NCBLK * H_ + h;
    float m = neg;

    const int seg_a[3] = { lo, e1, e2 };
    const int seg_b[3] = { s1, s2, hi };
    #pragma unroll
    for (int s = 0; s < 3; s++) {
        const int a = seg_a[s], bnd = seg_b[s];
        if (a >= bnd) continue;
        int a16 = (a + 15) & ~15;
        int b16 = bnd & ~15;
        if (a16 >= b16) {
            for (int t = a; t < bnd; t++) m = fmaxf(m, tb[(size_t)t * H_]);
            continue;
        }
        for (int t = a; t < a16; t++) m = fmaxf(m, tb[(size_t)t * H_]);
        const int j0 = a16 >> 4, j1 = b16 >> 4;
        const int jc0 = (j0 + 15) & ~15;
        const int jc1 = j1 & ~15;
        if (jc0 >= jc1) {
            for (int j = j0; j < j1; j++) m = fmaxf(m, bb[(size_t)j * H_]);
        } else {
            for (int j = j0; j < jc0; j++) m = fmaxf(m, bb[(size_t)j * H_]);
            for (int c = (jc0 >> 4); c < (jc1 >> 4); c++)
                m = fmaxf(m, cbb[(size_t)c * H_]);
            for (int j = jc1; j < j1; j++) m = fmaxf(m, bb[(size_t)j * H_]);
        }
        for (int t = b16; t < bnd; t++) m = fmaxf(m, tb[(size_t)t * H_]);
    }

    const int allneg = __syncthreads_and(m == neg);
    g_ctx[(size_t)br * H_ + h] = allneg ? 0.0f : tf32r(m);
}

// ---------------------------------------------------------------------------
// Shared GEMM helpers.
// ---------------------------------------------------------------------------
__device__ __forceinline__ void cp_async16(uint32_t dst, const void* src) {
    asm volatile("cp.async.cg.shared.global [%0], [%1], 16;\n"
                 :: "r"(dst), "l"(src));
}

__device__ __forceinline__ void mma_tf32(float* c, const uint32_t* a, const uint32_t* b) {
    asm volatile(
        "mma.sync.aligned.m16n8k8.row.col.f32.tf32.tf32.f32 "
        "{%0,%1,%2,%3}, {%4,%5,%6,%7}, {%8,%9}, {%0,%1,%2,%3};"
        : "+f"(c[0]), "+f"(c[1]), "+f"(c[2]), "+f"(c[3])
        : "r"(a[0]), "r"(a[1]), "r"(a[2]), "r"(a[3]), "r"(b[0]), "r"(b[1]));
}

// ---------------------------------------------------------------------------
// GEMM1 with FUSED GATHER (R16-proven): A row m = [sr[hid]|sr[tid]|ctx[m]].
// BM=128, BN=64, BK=32, 8 warps of 32x32, ReLU + tf32-round epilogue.
// ---------------------------------------------------------------------------
__global__ void __launch_bounds__(256)
k_gemm1(const float* __restrict__ sr, const float* __restrict__ ctx,
        const int* __restrict__ hti, const float* __restrict__ Bw,
        const float* __restrict__ bias, float* __restrict__ C) {
    constexpr int BM = 128, BN = 64, BK = 32, WM = 32, WN = 32;
    constexpr int WARPS_M = BM / WM;                 // 4
    constexpr int ASTR = BK + 4, BSTR = BN + 8;
    constexpr int MT = WM / 16, NTL = WN / 8;        // 2, 4
    constexpr int ASZ = BM * ASTR, BSZ = BK * BSTR;

    extern __shared__ float dsm[];
    float* As = dsm;
    float* Bs = dsm + 2 * ASZ;

    const int tid = threadIdx.x;
    const int bm = blockIdx.y * BM;
    const int bn = blockIdx.x * BN;
    const int wid = tid >> 5, lane = tid & 31;
    const int gid = lane >> 2, tig = lane & 3;
    const int wm0 = (wid % WARPS_M) * WM;
    const int wn0 = (wid / WARPS_M) * WN;

    const int r0 = tid >> 3;            // 0..31
    const int ac4 = (tid & 7) * 4;      // 0,4,..,28
    int hid[4], tid_[4];
    #pragma unroll
    for (int j = 0; j < 4; j++) {
        const int r = bm + r0 + j * 32;
        hid[j]  = hti[r * 2 + 0];
        tid_[j] = hti[r * 2 + 1];
    }

    float acc[MT][NTL][4];
    #pragma unroll
    for (int i = 0; i < MT; i++)
        #pragma unroll
        for (int j = 0; j < NTL; j++)
            #pragma unroll
            for (int q = 0; q < 4; q++) acc[i][j][q] = 0.0f;

    auto load_stage = [&](int s, int kk) {
        const int sec = kk >> 8;
        const int ko = (kk & 255) + ac4;
        #pragma unroll
        for (int j = 0; j < 4; j++) {
            const int r = r0 + j * 32;
            const float* src =
                (sec == 0) ? sr + (size_t)hid[j] * H_ + ko :
                (sec == 1) ? sr + (size_t)tid_[j] * H_ + ko :
                             ctx + (size_t)(bm + r) * H_ + ko;
            cp_async16((uint32_t)__cvta_generic_to_shared(&As[s * ASZ + r * ASTR + ac4]),
                       src);
        }
        #pragma unroll
        for (int j = 0; j < 2; j++) {    // B: 32 rows x 64 floats
            int i = tid + j * 256;
            int r = i >> 4, c4 = (i & 15) * 4;
            cp_async16((uint32_t)__cvta_generic_to_shared(&Bs[s * BSZ + r * BSTR + c4]),
                       Bw + (size_t)(kk + r) * DFF + bn + c4);
        }
        asm volatile("cp.async.commit_group;\n" ::: "memory");
    };

    constexpr int nk = DIN / BK;        // 24
    load_stage(0, 0);
    int s = 0;
    for (int kk = 0; kk < nk; kk++) {
        if (kk + 1 < nk) {
            load_stage(s ^ 1, (kk + 1) * BK);
            asm volatile("cp.async.wait_group 1;\n" ::: "memory");
        } else {
            asm volatile("cp.async.wait_group 0;\n" ::: "memory");
        }
        __syncthreads();

        #pragma unroll
        for (int k8 = 0; k8 < BK / 8; k8++) {
            uint32_t af[MT][4];
            uint32_t bf[NTL][2];
            #pragma unroll
            for (int mt = 0; mt < MT; mt++) {
                const uint32_t* p = (const uint32_t*)
                    &As[s * ASZ + (wm0 + mt * 16 + gid) * ASTR + k8 * 8 + tig];
                af[mt][0] = p[0];
                af[mt][1] = p[8 * ASTR];
                af[mt][2] = p[4];
                af[mt][3] = p[8 * ASTR + 4];
            }
            #pragma unroll
            for (int nt = 0; nt < NTL; nt++) {
                const uint32_t* p = (const uint32_t*)
                    &Bs[s * BSZ + (k8 * 8 + tig) * BSTR + wn0 + nt * 8 + gid];
                bf[nt][0] = p[0];
                bf[nt][1] = p[4 * BSTR];
            }
            #pragma unroll
            for (int mt = 0; mt < MT; mt++)
                #pragma unroll
                for (int nt = 0; nt < NTL; nt++)
                    mma_tf32(acc[mt][nt], af[mt], bf[nt]);
        }
        __syncthreads();
        s ^= 1;
    }

    #pragma unroll
    for (int mt = 0; mt < MT; mt++) {
        const int m0 = bm + wm0 + mt * 16 + gid;
        #pragma unroll
        for (int nt = 0; nt < NTL; nt++) {
            const int n0 = bn + wn0 + nt * 8 + 2 * tig;
            const float bv0 = bias[n0], bv1 = bias[n0 + 1];
            float v0 = tf32r(fmaxf(acc[mt][nt][0] + bv0, 0.0f));
            float v1 = tf32r(fmaxf(acc[mt][nt][1] + bv1, 0.0f));
            float v2 = tf32r(fmaxf(acc[mt][nt][2] + bv0, 0.0f));
            float v3 = tf32r(fmaxf(acc[mt][nt][3] + bv1, 0.0f));
            *(float2*)(C + (size_t)m0 * DFF + n0)       = make_float2(v0, v1);
            *(float2*)(C + (size_t)(m0 + 8) * DFF + n0) = make_float2(v2, v3);
        }
    }
}

// ---------------------------------------------------------------------------
// GEMM2 with ATOMIC split-K: partials RED.ADD.F32 directly into out
// (pre-initialized with bias by k_front). No partial buffers, no reduce pass.
// ---------------------------------------------------------------------------
template <int BM, int BN, int BK, int WM, int WN>
__global__ void __launch_bounds__((BM / WM) * (BN / WN) * 32)
k_gemm2a(const float* __restrict__ A, const float* __restrict__ Bw,
         float* __restrict__ C, int M, int N, int K, int Ksplit) {
    constexpr int WARPS_M = BM / WM;
    constexpr int WARPS_N = BN / WN;
    constexpr int NT = WARPS_M * WARPS_N * 32;
    constexpr int ASTR = BK + 4;
    constexpr int BSTR = BN + 8;
    constexpr int MT = WM / 16;
    constexpr int NTL = WN / 8;
    constexpr int LDA = (BM * BK / 4) / NT;
    constexpr int LDB = (BK * BN / 4) / NT;
    constexpr int ASZ = BM * ASTR;
    constexpr int BSZ = BK * BSTR;

    extern __shared__ float dsm[];
    float* As = dsm;
    float* Bs = dsm + 2 * ASZ;

    const int tid = threadIdx.x;
    const int bm = blockIdx.y * BM;
    const int bn = blockIdx.x * BN;
    const int k0 = blockIdx.z * Ksplit;
    const int wid = tid >> 5, lane = tid & 31;
    const int gid = lane >> 2, tig = lane & 3;
    const int wm0 = (wid % WARPS_M) * WM;
    const int wn0 = (wid / WARPS_M) * WN;

    float acc[MT][NTL][4];
    #pragma unroll
    for (int i = 0; i < MT; i++)
        #pragma unroll
        for (int j = 0; j < NTL; j++)
            #pragma unroll
            for (int q = 0; q < 4; q++) acc[i][j][q] = 0.0f;

    auto load_stage = [&](int s, int kk) {
        #pragma unroll
        for (int j = 0; j < LDA; j++) {
            int i = tid + j * NT;
            int r = i / (BK / 4), c4 = i % (BK / 4);
            cp_async16((uint32_t)__cvta_generic_to_shared(&As[s * ASZ + r * ASTR + c4 * 4]),
                       A + (size_t)(bm + r) * K + kk + c4 * 4);
        }
        #pragma unroll
        for (int j = 0; j < LDB; j++) {
            int i = tid + j * NT;
            int r = i / (BN / 4), c4 = i % (BN / 4);
            cp_async16((uint32_t)__cvta_generic_to_shared(&Bs[s * BSZ + r * BSTR + c4 * 4]),
                       Bw + (size_t)(kk + r) * N + bn + c4 * 4);
        }
        asm volatile("cp.async.commit_group;\n" ::: "memory");
    };

    const int nk = Ksplit / BK;
    load_stage(0, k0);
    int s = 0;
    for (int kk = 0; kk < nk; kk++) {
        if (kk + 1 < nk) {
            load_stage(s ^ 1, k0 + (kk + 1) * BK);
            asm volatile("cp.async.wait_group 1;\n" ::: "memory");
        } else {
            asm volatile("cp.async.wait_group 0;\n" ::: "memory");
        }
        __syncthreads();

        #pragma unroll
        for (int k8 = 0; k8 < BK / 8; k8++) {
            uint32_t af[MT][4];
            uint32_t bf[NTL][2];
            #pragma unroll
            for (int mt = 0; mt < MT; mt++) {
                const uint32_t* p = (const uint32_t*)
                    &As[s * ASZ + (wm0 + mt * 16 + gid) * ASTR + k8 * 8 + tig];
                af[mt][0] = p[0];
                af[mt][1] = p[8 * ASTR];
                af[mt][2] = p[4];
                af[mt][3] = p[8 * ASTR + 4];
            }
            #pragma unroll
            for (int nt = 0; nt < NTL; nt++) {
                const uint32_t* p = (const uint32_t*)
                    &Bs[s * BSZ + (k8 * 8 + tig) * BSTR + wn0 + nt * 8 + gid];
                bf[nt][0] = p[0];
                bf[nt][1] = p[4 * BSTR];
            }
            #pragma unroll
            for (int mt = 0; mt < MT; mt++)
                #pragma unroll
                for (int nt = 0; nt < NTL; nt++)
                    mma_tf32(acc[mt][nt], af[mt], bf[nt]);
        }
        __syncthreads();
        s ^= 1;
    }

    // Atomic accumulate into out (bias already there). RED.ADD.F32, no return.
    #pragma unroll
    for (int mt = 0; mt < MT; mt++) {
        const int m0 = bm + wm0 + mt * 16 + gid;
        #pragma unroll
        for (int nt = 0; nt < NTL; nt++) {
            const int n0 = bn + wn0 + nt * 8 + 2 * tig;
            atomicAdd(C + (size_t)m0 * N + n0,           acc[mt][nt][0]);
            atomicAdd(C + (size_t)m0 * N + n0 + 1,       acc[mt][nt][1]);
            atomicAdd(C + (size_t)(m0 + 8) * N + n0,     acc[mt][nt][2]);
            atomicAdd(C + (size_t)(m0 + 8) * N + n0 + 1, acc[mt][nt][3]);
        }
    }
}

// ---------------------------------------------------------------------------
// Input order per setup_inputs dict:
//  0 token_reps f32 (B,S,H)      1 token_masks bool (B,S)   2 span_reps f32 (B,NS,H)
//  3 span_ids  i32 (B,NS,2)      4 rel_ids   i32 (B,NR,2)   5 rel_masks bool (B,NR)
//  6 neg_limit f32 scalar        7 W1 (768,3072)  8 b1 (3072,)
//  9 W2 (3072,256)              10 b2 (256,)
// Output: f32 (B, NR, H) = 524288 (2*512*256)
// ---------------------------------------------------------------------------
extern "C" void kernel_launch(void* const* d_in, const int* in_sizes, int n_in,
                              void* d_out, int out_size) {
    const float* tok   = (const float*)d_in[0];
    const float* spans = (const float*)d_in[2];
    const int*   sids  = (const int*)d_in[3];
    const int*   rids  = (const int*)d_in[4];
    const float* negp  = (const float*)d_in[6];
    const float* W1    = (const float*)d_in[7];
    const float* b1    = (const float*)d_in[8];
    const float* W2    = (const float*)d_in[9];
    const float* b2    = (const float*)d_in[10];
    float* out = (float*)d_out;

    float *ctx, *sr, *hbuf, *w1r, *w2r;
    int* hti;
    cudaGetSymbolAddress((void**)&ctx,  g_ctx);
    cudaGetSymbolAddress((void**)&sr,   g_sr);
    cudaGetSymbolAddress((void**)&hti,  g_hti);
    cudaGetSymbolAddress((void**)&hbuf, g_h);
    cudaGetSymbolAddress((void**)&w1r,  g_w1r);
    cudaGetSymbolAddress((void**)&w2r,  g_w2r);

    constexpr int GSMEM = (2 * (128 * 36) + 2 * (32 * 72)) * 4;   // 55296
    cudaFuncSetAttribute(k_gemm1, cudaFuncAttributeMaxDynamicSharedMemorySize, GSMEM);
    cudaFuncSetAttribute(k_gemm2a<128, 64, 32, 32, 32>,
                         cudaFuncAttributeMaxDynamicSharedMemorySize, GSMEM);

    // Front: round(W1,W2,spans) + fine blkmax + out=bias init (one launch)
    k_front<<<NB_ROUND + NB_BMAX + NB_OINIT, 256>>>(W1, w1r, W2, w2r, spans, sr,
                                                    tok, negp, b2, out);
    k_blkmax2<<<B_ * NCBLK, H_>>>();
    k_rel<<<B_ * NR_, H_>>>(tok, sids, rids, negp);

    // GEMM1 (fused gather): relu([sr[h]|sr[t]|ctx] @ W1 + b1) -> 768 CTAs
    k_gemm1<<<dim3(DFF / 64, (B_ * NR_) / 128), 256, GSMEM>>>(sr, ctx, hti,
                                                              w1r, b1, hbuf);
    // GEMM2: split-K=8, atomic accumulate into out -> 512 CTAs, no reduce pass
    k_gemm2a<128, 64, 32, 32, 32>
        <<<dim3(H_ / 64, (B_ * NR_) / 128, KSPLIT), 256, GSMEM>>>(hbuf, w2r, out,
                                                                  B_ * NR_, H_,
                                                                  DFF, DFF / KSPLIT);
}